// round 3
// baseline (speedup 1.0000x reference)
#include <cuda_runtime.h>

#define HIDDEN 128
#define NNODES 50000
#define NEDGES 640000

// Per-node projections: P[n][0:128] = W1a*z[n] + b1  (u),  P[n][128:256] = W1b*z[n]  (v)
__device__ float g_P[NNODES * 256];

// ---------------------------------------------------------------------------
// Packed f32x2 helpers (sm_103a FFMA2 — only reachable via PTX fma.rn.f32x2)
// ---------------------------------------------------------------------------
__device__ __forceinline__ unsigned long long pack2(float lo, float hi) {
    unsigned long long r;
    asm("mov.b64 %0, {%1, %2};" : "=l"(r) : "f"(lo), "f"(hi));
    return r;
}
__device__ __forceinline__ void ffma2(unsigned long long& d,
                                      unsigned long long a,
                                      unsigned long long b) {
    asm("fma.rn.f32x2 %0, %1, %2, %0;" : "+l"(d) : "l"(a), "l"(b));
}
__device__ __forceinline__ float2 unpack2(unsigned long long v) {
    float2 r;
    asm("mov.b64 {%0, %1}, %2;" : "=f"(r.x), "=f"(r.y) : "l"(v));
    return r;
}

// ---------------------------------------------------------------------------
// Node GEMM: P[n][j] = sum_k W1T[j][k] * z[n][k]  (+ bias1[j] for j<128)
// W1T[j][k] = W1[(j&127)*256 + (j>=128 ? 128 : 0) + k]   (W1 is [128,256] row-major)
// 128 nodes x 128 cols per block, BK=16, 256 threads, 8x8 micro-tile.
// z staged DUPLICATED in smem so FFMA2 a-operands are ready dup-pairs (no MOVs);
// b-pairs are natural adjacent floats from ws. 2 FMA/instr -> 128 FMA/cyc/SM.
// ---------------------------------------------------------------------------
#define BK 16

__global__ __launch_bounds__(256, 2) void node_gemm(
    const float* __restrict__ z,
    const float* __restrict__ W1,
    const float* __restrict__ bias1)
{
    __shared__ float2 zs2[BK][128];   // duplicated: zs2[k][r] = (z, z)
    __shared__ float  ws[BK][128];

    const int j0 = blockIdx.x * 128;     // 0 (u-half) or 128 (v-half)
    const int n0 = blockIdx.y * 128;
    const int tid = threadIdx.x;
    const int tx = tid & 15;             // col micro-tile: cols j0 + tx*8 .. +7
    const int ty = tid >> 4;             // row micro-tile: nodes n0 + ty*8 .. +7

    // Cooperative load: 2048 floats per operand per tile = 8 floats/thread.
    const int ln = tid >> 1;             // 0..127 row within tile
    const int lk = (tid & 1) * 8;        // 0 or 8

    const bool zrow_ok = (n0 + ln) < NNODES;
    const float* zg = z + (size_t)(n0 + ln) * HIDDEN + lk;
    const float* wg = W1 + (size_t)ln * 256 + j0 + lk;   // row (j-j0)=ln, col j0+k

    unsigned long long acc[8][4];
#pragma unroll
    for (int i = 0; i < 8; i++)
#pragma unroll
        for (int jp = 0; jp < 4; jp++) acc[i][jp] = 0ull;

    // Prefetch tile 0 into registers (2 float4 per operand per thread).
    float4 zr0, zr1, wr0, wr1;
    zr0 = zrow_ok ? *(const float4*)zg : make_float4(0.f, 0.f, 0.f, 0.f);
    zr1 = zrow_ok ? *(const float4*)(zg + 4) : make_float4(0.f, 0.f, 0.f, 0.f);
    wr0 = *(const float4*)wg;
    wr1 = *(const float4*)(wg + 4);

#pragma unroll 1
    for (int kt = 0; kt < HIDDEN / BK; kt++) {
        // Stage tile to smem: z duplicated, w plain.
        zs2[lk + 0][ln] = make_float2(zr0.x, zr0.x);
        zs2[lk + 1][ln] = make_float2(zr0.y, zr0.y);
        zs2[lk + 2][ln] = make_float2(zr0.z, zr0.z);
        zs2[lk + 3][ln] = make_float2(zr0.w, zr0.w);
        zs2[lk + 4][ln] = make_float2(zr1.x, zr1.x);
        zs2[lk + 5][ln] = make_float2(zr1.y, zr1.y);
        zs2[lk + 6][ln] = make_float2(zr1.z, zr1.z);
        zs2[lk + 7][ln] = make_float2(zr1.w, zr1.w);
        ws[lk + 0][ln] = wr0.x; ws[lk + 1][ln] = wr0.y;
        ws[lk + 2][ln] = wr0.z; ws[lk + 3][ln] = wr0.w;
        ws[lk + 4][ln] = wr1.x; ws[lk + 5][ln] = wr1.y;
        ws[lk + 6][ln] = wr1.z; ws[lk + 7][ln] = wr1.w;
        __syncthreads();

        // Prefetch next tile while computing this one.
        if (kt + 1 < HIDDEN / BK) {
            const float* zn = zg + (kt + 1) * BK;
            const float* wn = wg + (kt + 1) * BK;
            zr0 = zrow_ok ? *(const float4*)zn : make_float4(0.f, 0.f, 0.f, 0.f);
            zr1 = zrow_ok ? *(const float4*)(zn + 4) : make_float4(0.f, 0.f, 0.f, 0.f);
            wr0 = *(const float4*)wn;
            wr1 = *(const float4*)(wn + 4);
        }

#pragma unroll
        for (int k = 0; k < BK; k++) {
            // a dup-pairs: LDS.128 over zs2 gives (a_i,a_i,a_{i+1},a_{i+1}).
            const unsigned long long* ap =
                (const unsigned long long*)&zs2[k][ty * 8];   // 8 dup-pairs, 4 LDS.128
            // b natural pairs: LDS.128 over ws gives (b_j,b_{j+1},b_{j+2},b_{j+3}).
            const unsigned long long* bp =
                (const unsigned long long*)&ws[k][tx * 8];    // 4 pairs, 2 LDS.128

            unsigned long long b0 = bp[0], b1 = bp[1], b2 = bp[2], b3 = bp[3];
#pragma unroll
            for (int i = 0; i < 8; i++) {
                unsigned long long a = ap[i];
                ffma2(acc[i][0], a, b0);
                ffma2(acc[i][1], a, b1);
                ffma2(acc[i][2], a, b2);
                ffma2(acc[i][3], a, b3);
            }
        }
        __syncthreads();
    }

    // Epilogue: fold bias1 into the u-half (j0==0), vectorized stores.
    float bv[8];
#pragma unroll
    for (int q = 0; q < 8; q++) bv[q] = 0.f;
    if (j0 == 0) {
        float4 t0 = *(const float4*)(bias1 + tx * 8);
        float4 t1 = *(const float4*)(bias1 + tx * 8 + 4);
        bv[0] = t0.x; bv[1] = t0.y; bv[2] = t0.z; bv[3] = t0.w;
        bv[4] = t1.x; bv[5] = t1.y; bv[6] = t1.z; bv[7] = t1.w;
    }

#pragma unroll
    for (int i = 0; i < 8; i++) {
        int n = n0 + ty * 8 + i;
        if (n < NNODES) {
            float2 p0 = unpack2(acc[i][0]);
            float2 p1 = unpack2(acc[i][1]);
            float2 p2 = unpack2(acc[i][2]);
            float2 p3 = unpack2(acc[i][3]);
            float4 o0 = make_float4(p0.x + bv[0], p0.y + bv[1], p1.x + bv[2], p1.y + bv[3]);
            float4 o1 = make_float4(p2.x + bv[4], p2.y + bv[5], p3.x + bv[6], p3.y + bv[7]);
            float* dst = &g_P[(size_t)n * 256 + j0 + tx * 8];
            *(float4*)dst = o0;
            *(float4*)(dst + 4) = o1;
        }
    }
}

// ---------------------------------------------------------------------------
// Edge kernel: one warp per edge (L2-bandwidth bound, ~1KB/edge from L2).
// Inline int64/int32 edge_index detect: each warp ballots the high words of
// the first 32 entries (same 128B line for all warps -> L1 hit, ~free).
// lane l handles cols 4l..4l+3: acc = sum relu(u_c + v_c) * W2_c ; warp-reduce.
// (bias1 already folded into u.)
// ---------------------------------------------------------------------------
__global__ __launch_bounds__(256) void edge_kernel(
    const void* __restrict__ eidx,
    const float* __restrict__ W2,
    const float* __restrict__ bias2,
    float* __restrict__ out)
{
    const int warp = (int)((blockIdx.x * blockDim.x + threadIdx.x) >> 5);
    const int lane = threadIdx.x & 31;
    if (warp >= NEDGES) return;

    // Per-warp dtype detect (int64 => high words all zero).
    const unsigned int* hw = (const unsigned int*)eidx;
    unsigned int hv = hw[2 * lane + 1];
    const bool is64 = (__ballot_sync(0xffffffffu, hv != 0u) == 0u);

    int s, d;
    if (is64) {
        const long long* p = (const long long*)eidx;
        s = (int)p[warp];
        d = (int)p[NEDGES + warp];
    } else {
        const int* p = (const int*)eidx;
        s = p[warp];
        d = p[NEDGES + warp];
    }

    float4 u = *(const float4*)&g_P[(size_t)s * 256 + lane * 4];
    float4 v = *(const float4*)&g_P[(size_t)d * 256 + 128 + lane * 4];
    float4 w = ((const float4*)W2)[lane];

    float acc;
    acc  = fmaxf(u.x + v.x, 0.0f) * w.x;
    acc += fmaxf(u.y + v.y, 0.0f) * w.y;
    acc += fmaxf(u.z + v.z, 0.0f) * w.z;
    acc += fmaxf(u.w + v.w, 0.0f) * w.w;

#pragma unroll
    for (int o = 16; o; o >>= 1)
        acc += __shfl_xor_sync(0xffffffffu, acc, o);

    if (lane == 0) out[warp] = acc + bias2[0];
}

// ---------------------------------------------------------------------------
// Inputs (metadata order): z, W1, bias1, W2, bias2, edge_index
// ---------------------------------------------------------------------------
extern "C" void kernel_launch(void* const* d_in, const int* in_sizes, int n_in,
                              void* d_out, int out_size)
{
    const float* z  = (const float*)d_in[0];
    const float* W1 = (const float*)d_in[1];
    const float* b1 = (const float*)d_in[2];
    const float* W2 = (const float*)d_in[3];
    const float* b2 = (const float*)d_in[4];
    const void*  ei = d_in[5];

    dim3 grid(2, (NNODES + 127) / 128);   // 2 x 391
    node_gemm<<<grid, 256>>>(z, W1, b1);

    edge_kernel<<<NEDGES / 8, 256>>>(ei, W2, b2, (float*)d_out);
}